// round 4
// baseline (speedup 1.0000x reference)
#include <cuda_runtime.h>
#include <cuda_bf16.h>
#include <cstdint>

// Problem constants
#define NB 16           // B
#define SS 1024         // S
#define EE 8192         // E
#define DD 512          // D  (= H*DK)
#define HH 8            // H
#define DKK 64          // DK
#define LL 2            // L
#define NN (NB*SS)      // 16384 nodes
#define BEE (NB*EE)     // 131072 edges (padded)

// ---------------- scratch (device globals; no allocation allowed) -------------
__device__ float g_Q[NN*DD];
__device__ float g_K[NN*DD];
__device__ float g_V[NN*DD];
__device__ float g_AGG[NN*DD];
__device__ float g_LIN[NN*DD];
__device__ int   g_src[BEE];
__device__ int   g_tgt[BEE];
__device__ int   g_dr[BEE];
__device__ int   g_da[BEE];
__device__ int   g_rp[BEE];
__device__ float g_ev[BEE*HH];        // logit, then exp value
__device__ unsigned g_mkey[NN*HH];    // monotone-key float max
__device__ float g_denom[NN*HH];
__device__ int   g_starts[NB+1];      // g_starts[NB] = edge_total

// ---------------- monotone float<->uint key (for atomicMax on floats) ---------
__device__ __forceinline__ unsigned fkey(float f) {
    unsigned u = __float_as_uint(f);
    return (u & 0x80000000u) ? ~u : (u | 0x80000000u);
}
__device__ __forceinline__ float funkey(unsigned k) {
    unsigned u = (k & 0x80000000u) ? (k & 0x7fffffffu) : ~k;
    return __uint_as_float(u);
}

// ---------------- prep: exclusive scan of edge_len (B=16) --------------------
__global__ void prep_kernel(const int* __restrict__ edge_len) {
    if (threadIdx.x == 0 && blockIdx.x == 0) {
        int s = 0;
        for (int b = 0; b < NB; b++) { g_starts[b] = s; s += edge_len[b]; }
        g_starts[NB] = s;
    }
}

// ---------------- flatten ragged edges ---------------------------------------
__global__ void flatten_kernel(const int* __restrict__ edge_len,
                               const int* __restrict__ edge_index,
                               const int* __restrict__ drl,
                               const int* __restrict__ dac,
                               const int* __restrict__ rpp) {
    int i = blockIdx.x * blockDim.x + threadIdx.x;
    if (i >= NB*EE) return;
    int b = i / EE, e = i % EE;
    if (e < edge_len[b]) {
        int fp = g_starts[b] + e;
        g_src[fp] = edge_index[(size_t)i*2 + 0] + b*SS;
        g_tgt[fp] = edge_index[(size_t)i*2 + 1] + b*SS;
        g_dr[fp]  = drl[i];
        g_da[fp]  = dac[i];
        g_rp[fp]  = rpp[i];
    }
}

// ---------------- zero fill --------------------------------------------------
__global__ void zero_f(float* __restrict__ p, int n) {
    int i = blockIdx.x * blockDim.x + threadIdx.x;
    if (i < n) p[i] = 0.f;
}

__global__ void layer_init() {
    int i = blockIdx.x * blockDim.x + threadIdx.x;
    if (i < NN*DD) g_AGG[i] = 0.f;
    if (i < NN*HH) { g_mkey[i] = 0u; g_denom[i] = 0.f; }
}

// ---------------- TF32 helpers -----------------------------------------------
__device__ __forceinline__ void tf32split(float f, float& hi, float& lo) {
    unsigned h; asm("cvt.rna.tf32.f32 %0, %1;" : "=r"(h) : "f"(f));
    float hf = __uint_as_float(h);
    float lf = f - hf;
    unsigned l; asm("cvt.rna.tf32.f32 %0, %1;" : "=r"(l) : "f"(lf));
    hi = hf; lo = __uint_as_float(l);
}

__device__ __forceinline__ void mma8(float* c, const unsigned* a, const unsigned* b) {
    asm("mma.sync.aligned.m16n8k8.row.col.f32.tf32.tf32.f32 "
        "{%0,%1,%2,%3}, {%4,%5,%6,%7}, {%8,%9}, {%0,%1,%2,%3};"
        : "+f"(c[0]), "+f"(c[1]), "+f"(c[2]), "+f"(c[3])
        : "r"(a[0]), "r"(a[1]), "r"(a[2]), "r"(a[3]), "r"(b[0]), "r"(b[1]));
}

// ---------------- Tensor-core GEMM: C = A[M,512] @ B[512,512] (+res) ---------
// 128x128 CTA tile, BK=16, 256 threads (8 warps, 2x4), warp tile 64x32.
// TF32 3x split (hi*hi + hi*lo + lo*hi). hi/lo split once at smem staging.
// Double-buffered; row stride 136 floats -> conflict-free fragment LDS.
#define RSF 136
#define TAF (16*RSF)
#define TG_SMEM (8*TAF*4)   // 69632 bytes

template <bool RES>
__device__ __forceinline__ void tgemm_body(const float* __restrict__ A,
                                           const float* __restrict__ B,
                                           float* __restrict__ C,
                                           const float* __restrict__ res,
                                           int bx, int by) {
    extern __shared__ float sm[];
    float* AHs = sm;             // [2][16][RSF]
    float* ALs = sm + 2*TAF;
    float* BHs = sm + 4*TAF;
    float* BLs = sm + 6*TAF;

    const int tid  = threadIdx.x;
    const int w    = tid >> 5;
    const int lane = tid & 31;
    const int gid  = lane >> 2;      // 0..7
    const int tig  = lane & 3;       // 0..3
    const int wm   = (w & 1) * 64;   // warp M offset in tile
    const int wn   = (w >> 1) * 32;  // warp N offset in tile

    // global fetch coords (fixed)
    const int a_m0 = tid >> 2, a_m1 = a_m0 + 64, a_kq = (tid & 3) * 4;
    const int b_k0 = tid >> 5, b_k1 = b_k0 + 8,  b_nq = (tid & 31) * 4;

    const float* Aptr = A + (size_t)by * 128 * 512;
    const float* Bptr = B + bx * 128;

    float acc[4][4][4];
    #pragma unroll
    for (int i = 0; i < 4; i++)
        #pragma unroll
        for (int j = 0; j < 4; j++)
            #pragma unroll
            for (int r = 0; r < 4; r++) acc[i][j][r] = 0.f;

    float4 ra0, ra1, rb0, rb1;
    auto fetch = [&](int kt) {
        ra0 = *(const float4*)(Aptr + (size_t)a_m0 * 512 + kt + a_kq);
        ra1 = *(const float4*)(Aptr + (size_t)a_m1 * 512 + kt + a_kq);
        rb0 = *(const float4*)(Bptr + (size_t)(kt + b_k0) * 512 + b_nq);
        rb1 = *(const float4*)(Bptr + (size_t)(kt + b_k1) * 512 + b_nq);
    };
    auto stage = [&](int buf) {
        float* ah = AHs + buf*TAF;  float* al = ALs + buf*TAF;
        float* bh = BHs + buf*TAF;  float* bl = BLs + buf*TAF;
        const float* pa0 = (const float*)&ra0;
        const float* pa1 = (const float*)&ra1;
        #pragma unroll
        for (int j = 0; j < 4; j++) {
            float h, l;
            tf32split(pa0[j], h, l);
            ah[(a_kq+j)*RSF + a_m0] = h;  al[(a_kq+j)*RSF + a_m0] = l;
            tf32split(pa1[j], h, l);
            ah[(a_kq+j)*RSF + a_m1] = h;  al[(a_kq+j)*RSF + a_m1] = l;
        }
        float4 h0, l0, h1, l1;
        tf32split(rb0.x, h0.x, l0.x); tf32split(rb0.y, h0.y, l0.y);
        tf32split(rb0.z, h0.z, l0.z); tf32split(rb0.w, h0.w, l0.w);
        tf32split(rb1.x, h1.x, l1.x); tf32split(rb1.y, h1.y, l1.y);
        tf32split(rb1.z, h1.z, l1.z); tf32split(rb1.w, h1.w, l1.w);
        *(float4*)&bh[b_k0*RSF + b_nq] = h0;  *(float4*)&bl[b_k0*RSF + b_nq] = l0;
        *(float4*)&bh[b_k1*RSF + b_nq] = h1;  *(float4*)&bl[b_k1*RSF + b_nq] = l1;
    };
    auto compute = [&](int buf) {
        const float* ahp = AHs + buf*TAF;  const float* alp = ALs + buf*TAF;
        const float* bhp = BHs + buf*TAF;  const float* blp = BLs + buf*TAF;
        #pragma unroll
        for (int s = 0; s < 2; s++) {
            const int kb = s * 8;
            unsigned bh[4][2], bl[4][2];
            #pragma unroll
            for (int nt = 0; nt < 4; nt++) {
                int n0 = wn + nt*8 + gid;
                bh[nt][0] = __float_as_uint(bhp[(kb+tig  )*RSF + n0]);
                bh[nt][1] = __float_as_uint(bhp[(kb+tig+4)*RSF + n0]);
                bl[nt][0] = __float_as_uint(blp[(kb+tig  )*RSF + n0]);
                bl[nt][1] = __float_as_uint(blp[(kb+tig+4)*RSF + n0]);
            }
            #pragma unroll
            for (int mt = 0; mt < 4; mt++) {
                int m0 = wm + mt*16 + gid;
                unsigned ah[4], al[4];
                ah[0] = __float_as_uint(ahp[(kb+tig  )*RSF + m0]);
                ah[1] = __float_as_uint(ahp[(kb+tig  )*RSF + m0+8]);
                ah[2] = __float_as_uint(ahp[(kb+tig+4)*RSF + m0]);
                ah[3] = __float_as_uint(ahp[(kb+tig+4)*RSF + m0+8]);
                al[0] = __float_as_uint(alp[(kb+tig  )*RSF + m0]);
                al[1] = __float_as_uint(alp[(kb+tig  )*RSF + m0+8]);
                al[2] = __float_as_uint(alp[(kb+tig+4)*RSF + m0]);
                al[3] = __float_as_uint(alp[(kb+tig+4)*RSF + m0+8]);
                #pragma unroll
                for (int nt = 0; nt < 4; nt++) {
                    mma8(acc[mt][nt], ah, bh[nt]);   // hi*hi
                    mma8(acc[mt][nt], ah, bl[nt]);   // hi*lo
                    mma8(acc[mt][nt], al, bh[nt]);   // lo*hi
                }
            }
        }
    };

    fetch(0);
    stage(0);
    __syncthreads();

    for (int kt = 0; kt < 512; kt += 16) {
        const int cur = (kt >> 4) & 1;
        const bool more = (kt + 16) < 512;
        if (more) fetch(kt + 16);        // non-blocking LDGs overlap HMMA
        compute(cur);
        if (more) stage(cur ^ 1);
        __syncthreads();
    }

    // Epilogue: c0,c1 -> (row gid, cols 2tig,2tig+1); c2,c3 -> row gid+8
    #pragma unroll
    for (int mt = 0; mt < 4; mt++) {
        #pragma unroll
        for (int nt = 0; nt < 4; nt++) {
            int r0 = by*128 + wm + mt*16 + gid;
            int cc = bx*128 + wn + nt*8 + tig*2;
            float2 v0 = make_float2(acc[mt][nt][0], acc[mt][nt][1]);
            float2 v1 = make_float2(acc[mt][nt][2], acc[mt][nt][3]);
            if (RES) {
                float2 q0 = *(const float2*)(res + (size_t)r0 * 512 + cc);
                float2 q1 = *(const float2*)(res + (size_t)(r0+8) * 512 + cc);
                v0.x += q0.x; v0.y += q0.y; v1.x += q1.x; v1.y += q1.y;
            }
            *(float2*)(C + (size_t)r0     * 512 + cc) = v0;
            *(float2*)(C + (size_t)(r0+8) * 512 + cc) = v1;
        }
    }
}

// Fused Q/K/V projection: blockIdx.z selects the weight/output pair.
__global__ void __launch_bounds__(256, 2)
qkv_gemm(const float* __restrict__ A,
         const float* __restrict__ Bq, const float* __restrict__ Bk,
         const float* __restrict__ Bv,
         float* __restrict__ Cq, float* __restrict__ Ck, float* __restrict__ Cv) {
    const float* B = (blockIdx.z == 0) ? Bq : (blockIdx.z == 1) ? Bk : Bv;
    float*       C = (blockIdx.z == 0) ? Cq : (blockIdx.z == 1) ? Ck : Cv;
    tgemm_body<false>(A, B, C, nullptr, blockIdx.x, blockIdx.y);
}

// Output projection with fused residual add.
__global__ void __launch_bounds__(256, 2)
o_gemm(const float* __restrict__ A, const float* __restrict__ B,
       float* __restrict__ C, const float* __restrict__ res) {
    tgemm_body<true>(A, B, C, res, blockIdx.x, blockIdx.y);
}

// ---------------- edge pass 1: logits + segment max --------------------------
// one warp per valid edge
__global__ void edge_logits(const float* __restrict__ dre,
                            const float* __restrict__ dae,
                            const float* __restrict__ rpe) {
    int warp = (blockIdx.x * blockDim.x + threadIdx.x) >> 5;
    int lane = threadIdx.x & 31;
    int total = g_starts[NB];
    if (warp >= total) return;
    int e = warp;
    int src = g_src[e], tgt = g_tgt[e];
    int d0 = lane * 2;
    int dr = g_dr[e], da = g_da[e], rp = g_rp[e];
    const float2 drv = *(const float2*)(dre + dr*DKK + d0);
    const float2 dav = *(const float2*)(dae + da*DKK + d0);
    const float2 rpv = *(const float2*)(rpe + rp*DKK + d0);
    float r0 = drv.x + dav.x + rpv.x;
    float r1 = drv.y + dav.y + rpv.y;
    #pragma unroll
    for (int h = 0; h < HH; h++) {
        const float2 kk = *(const float2*)(g_K + (size_t)src*DD + h*DKK + d0);
        const float2 qq = *(const float2*)(g_Q + (size_t)tgt*DD + h*DKK + d0);
        float p = qq.x * (kk.x + r0) + qq.y * (kk.y + r1);
        #pragma unroll
        for (int off = 16; off; off >>= 1) p += __shfl_xor_sync(0xffffffffu, p, off);
        if (lane == 0) {
            float lg = p * 0.125f;     // 1/sqrt(64)
            g_ev[(size_t)e*HH + h] = lg;
            atomicMax(&g_mkey[tgt*HH + h], fkey(lg));
        }
    }
}

// ---------------- edge pass 2: exp + segment sum -----------------------------
__global__ void edge_expsum() {
    int idx = blockIdx.x * blockDim.x + threadIdx.x;
    int total = g_starts[NB];
    if (idx >= total * HH) return;
    int e = idx >> 3;
    int h = idx & 7;
    int tgt = g_tgt[e];
    float m = funkey(g_mkey[tgt*HH + h]);
    float ev = __expf(g_ev[idx] - m);
    g_ev[idx] = ev;
    atomicAdd(&g_denom[tgt*HH + h], ev);
}

// ---------------- edge pass 3: alpha + scatter aggregation -------------------
// one warp per valid edge
__global__ void edge_aggregate(const float* __restrict__ dre,
                               const float* __restrict__ dae,
                               const float* __restrict__ rpe,
                               float* __restrict__ alpha_out) {
    int warp = (blockIdx.x * blockDim.x + threadIdx.x) >> 5;
    int lane = threadIdx.x & 31;
    int total = g_starts[NB];
    if (warp >= total) return;
    int e = warp;
    int src = g_src[e], tgt = g_tgt[e];
    int d0 = lane * 2;
    int dr = g_dr[e], da = g_da[e], rp = g_rp[e];
    const float2 drv = *(const float2*)(dre + dr*DKK + d0);
    const float2 dav = *(const float2*)(dae + da*DKK + d0);
    const float2 rpv = *(const float2*)(rpe + rp*DKK + d0);
    float r0 = drv.x + dav.x + rpv.x;
    float r1 = drv.y + dav.y + rpv.y;

    float al[HH];
    #pragma unroll
    for (int h = 0; h < HH; h++)
        al[h] = g_ev[(size_t)e*HH + h] / (g_denom[tgt*HH + h] + 1e-9f);
    if (lane < HH) alpha_out[(size_t)e*HH + lane] = al[lane];

    #pragma unroll
    for (int h = 0; h < HH; h++) {
        const float2 vv = *(const float2*)(g_V + (size_t)src*DD + h*DKK + d0);
        atomicAdd(&g_AGG[(size_t)tgt*DD + h*DKK + d0],     al[h] * (vv.x + r0));
        atomicAdd(&g_AGG[(size_t)tgt*DD + h*DKK + d0 + 1], al[h] * (vv.y + r1));
    }
}

// ---------------- LayerNorm (+ residual already fused in GEMM) ---------------
__global__ void ln_kernel(const float* __restrict__ x,
                          const float* __restrict__ scale,
                          const float* __restrict__ bias,
                          float* __restrict__ out, int do_relu) {
    int row = blockIdx.x;
    const float* xr = x + (size_t)row * DD;
    int t = threadIdx.x;               // 128 threads, 4 elems each
    float v[4];
    float s = 0.f;
    #pragma unroll
    for (int i = 0; i < 4; i++) { v[i] = xr[t + i*128]; s += v[i]; }
    __shared__ float red[4];
    #pragma unroll
    for (int off = 16; off; off >>= 1) s += __shfl_xor_sync(0xffffffffu, s, off);
    if ((t & 31) == 0) red[t >> 5] = s;
    __syncthreads();
    s = red[0] + red[1] + red[2] + red[3];
    float mu = s * (1.f / DD);
    float vs = 0.f;
    #pragma unroll
    for (int i = 0; i < 4; i++) { float d = v[i] - mu; vs += d*d; }
    __syncthreads();
    #pragma unroll
    for (int off = 16; off; off >>= 1) vs += __shfl_xor_sync(0xffffffffu, vs, off);
    if ((t & 31) == 0) red[t >> 5] = vs;
    __syncthreads();
    vs = red[0] + red[1] + red[2] + red[3];
    float rstd = rsqrtf(vs * (1.f / DD) + 1e-5f);
    float* orow = out + (size_t)row * DD;
    #pragma unroll
    for (int i = 0; i < 4; i++) {
        int d = t + i*128;
        float y = (v[i] - mu) * rstd * scale[d] + bias[d];
        if (do_relu) y = fmaxf(y, 0.f);
        orow[d] = y;
    }
}

// ---------------- host orchestration -----------------------------------------
extern "C" void kernel_launch(void* const* d_in, const int* in_sizes, int n_in,
                              void* d_out, int out_size) {
    const float* inp        = (const float*)d_in[0];
    const int*   edge_len   = (const int*)  d_in[2];
    const int*   edge_index = (const int*)  d_in[3];
    const int*   rp_in      = (const int*)  d_in[4];   // dep_rel_pos_edge_rep
    const int*   dr_in      = (const int*)  d_in[6];   // deprel_edge_rep
    const int*   da_in      = (const int*)  d_in[7];   // deparc_edge_rep
    const float* Wq         = (const float*)d_in[14];
    const float* Wk         = (const float*)d_in[15];
    const float* Wv         = (const float*)d_in[16];
    const float* Wo         = (const float*)d_in[17];
    const float* dre        = (const float*)d_in[18];
    const float* dae        = (const float*)d_in[19];
    const float* rpe        = (const float*)d_in[20];
    const float* ln_s       = (const float*)d_in[21];
    const float* ln_b       = (const float*)d_in[22];

    float* out   = (float*)d_out;
    float* reps  = out;                             // [L, N, D]
    float* attns = out + (size_t)LL * NN * DD;      // [L, BE, H]

    float *Qp, *Kp, *Vp, *AGGp, *LINp;
    cudaGetSymbolAddress((void**)&Qp,   g_Q);
    cudaGetSymbolAddress((void**)&Kp,   g_K);
    cudaGetSymbolAddress((void**)&Vp,   g_V);
    cudaGetSymbolAddress((void**)&AGGp, g_AGG);
    cudaGetSymbolAddress((void**)&LINp, g_LIN);

    cudaFuncSetAttribute(qkv_gemm, cudaFuncAttributeMaxDynamicSharedMemorySize, TG_SMEM);
    cudaFuncSetAttribute(o_gemm,   cudaFuncAttributeMaxDynamicSharedMemorySize, TG_SMEM);

    prep_kernel<<<1, 32>>>(edge_len);
    flatten_kernel<<<(NB*EE + 255)/256, 256>>>(edge_len, edge_index, dr_in, da_in, rp_in);
    zero_f<<<(LL*BEE*HH + 255)/256, 256>>>(attns, LL*BEE*HH);

    dim3 qkv_grid(4, 128, 3);        // N/128 x M/128 x {Q,K,V}
    dim3 gemm_grid(4, 128);
    const float* h = inp;
    for (int l = 0; l < LL; l++) {
        const size_t woff = (size_t)l * 512 * 512;
        qkv_gemm<<<qkv_grid, 256, TG_SMEM>>>(h, Wq + woff, Wk + woff, Wv + woff, Qp, Kp, Vp);

        layer_init<<<(NN*DD + 255)/256, 256>>>();

        const float* drl = dre + (size_t)l * 50 * DKK;
        const float* dal = dae + (size_t)l * 3  * DKK;
        const float* rpl = rpe + (size_t)l * 21 * DKK;

        edge_logits<<<BEE/8, 256>>>(drl, dal, rpl);
        edge_expsum<<<(BEE*HH + 255)/256, 256>>>();
        edge_aggregate<<<BEE/8, 256>>>(drl, dal, rpl, attns + (size_t)l * BEE * HH);

        o_gemm<<<gemm_grid, 256, TG_SMEM>>>(AGGp, Wo + woff, LINp, h);

        float* rep_l = reps + (size_t)l * NN * DD;
        ln_kernel<<<NN, 128>>>(LINp, ln_s + (size_t)l * DD, ln_b + (size_t)l * DD,
                               rep_l, (l < LL - 1) ? 1 : 0);
        h = rep_l;
    }
}

// round 11
// speedup vs baseline: 1.9443x; 1.9443x over previous
#include <cuda_runtime.h>
#include <cuda_bf16.h>
#include <cstdint>

// Problem constants
#define NB 16           // B
#define SS 1024         // S
#define EE 8192         // E
#define DD 512          // D  (= H*DK)
#define HH 8            // H
#define DKK 64          // DK
#define LL 2            // L
#define NN (NB*SS)      // 16384 nodes
#define BEE (NB*EE)     // 131072 edges (padded)

// ---------------- scratch (device globals; no allocation allowed) -------------
__device__ float g_Q[NN*DD];
__device__ float g_K[NN*DD];
__device__ float g_V[NN*DD];
__device__ float g_AGG[NN*DD];
__device__ float g_LIN[NN*DD];
__device__ __nv_bfloat16 g_Ah[NN*DD];     // activation hi split
__device__ __nv_bfloat16 g_Al[NN*DD];     // activation lo split
__device__ __nv_bfloat16 g_Wh[8*DD*DD];   // weights, transposed [n][k], hi
__device__ __nv_bfloat16 g_Wl[8*DD*DD];   // weights, transposed [n][k], lo
__device__ int   g_src[BEE];
__device__ int   g_tgt[BEE];
__device__ int   g_dr[BEE];
__device__ int   g_da[BEE];
__device__ int   g_rp[BEE];
__device__ float g_ev[BEE*HH];
__device__ unsigned g_mkey[NN*HH];
__device__ float g_denom[NN*HH];
__device__ int   g_starts[NB+1];

// ---------------- monotone float<->uint key -----------------------------------
__device__ __forceinline__ unsigned fkey(float f) {
    unsigned u = __float_as_uint(f);
    return (u & 0x80000000u) ? ~u : (u | 0x80000000u);
}
__device__ __forceinline__ float funkey(unsigned k) {
    unsigned u = (k & 0x80000000u) ? (k & 0x7fffffffu) : ~k;
    return __uint_as_float(u);
}

// ---------------- prep: exclusive scan of edge_len ----------------------------
__global__ void prep_kernel(const int* __restrict__ edge_len) {
    if (threadIdx.x == 0 && blockIdx.x == 0) {
        int s = 0;
        for (int b = 0; b < NB; b++) { g_starts[b] = s; s += edge_len[b]; }
        g_starts[NB] = s;
    }
}

// ---------------- flatten ragged edges ---------------------------------------
__global__ void flatten_kernel(const int* __restrict__ edge_len,
                               const int* __restrict__ edge_index,
                               const int* __restrict__ drl,
                               const int* __restrict__ dac,
                               const int* __restrict__ rpp) {
    int i = blockIdx.x * blockDim.x + threadIdx.x;
    if (i >= NB*EE) return;
    int b = i / EE, e = i % EE;
    if (e < edge_len[b]) {
        int fp = g_starts[b] + e;
        g_src[fp] = edge_index[(size_t)i*2 + 0] + b*SS;
        g_tgt[fp] = edge_index[(size_t)i*2 + 1] + b*SS;
        g_dr[fp]  = drl[i];
        g_da[fp]  = dac[i];
        g_rp[fp]  = rpp[i];
    }
}

// ---------------- zero fill --------------------------------------------------
__global__ void zero_f(float* __restrict__ p, int n) {
    int i = blockIdx.x * blockDim.x + threadIdx.x;
    if (i < n) p[i] = 0.f;
}

__global__ void layer_init() {
    int i = blockIdx.x * blockDim.x + threadIdx.x;
    if (i < NN*DD) g_AGG[i] = 0.f;
    if (i < NN*HH) { g_mkey[i] = 0u; g_denom[i] = 0.f; }
}

// ---------------- weight transpose + bf16 split -------------------------------
// W[l][k][n] -> g_Wh/g_Wl[g][n][k], g = l*4 + {q,k,v,o}
__global__ void split_w(const float* __restrict__ Wq, const float* __restrict__ Wk,
                        const float* __restrict__ Wv, const float* __restrict__ Wo) {
    __shared__ float t[32][33];
    int g = blockIdx.z, l = g >> 2, w = g & 3;
    const float* W = (w==0?Wq:w==1?Wk:w==2?Wv:Wo) + (size_t)l*DD*DD;
    __nv_bfloat16* oh = g_Wh + (size_t)g*DD*DD;
    __nv_bfloat16* ol = g_Wl + (size_t)g*DD*DD;
    int k0 = blockIdx.x*32, n0 = blockIdx.y*32;
    int tx = threadIdx.x, ty = threadIdx.y;
    #pragma unroll
    for (int i = 0; i < 4; i++)
        t[ty + i*8][tx] = W[(size_t)(k0 + ty + i*8)*DD + n0 + tx];
    __syncthreads();
    #pragma unroll
    for (int i = 0; i < 4; i++) {
        int n = n0 + ty + i*8, k = k0 + tx;
        float x = t[tx][ty + i*8];
        __nv_bfloat16 h = __float2bfloat16_rn(x);
        __nv_bfloat16 lo = __float2bfloat16_rn(x - __bfloat162float(h));
        oh[(size_t)n*DD + k] = h;
        ol[(size_t)n*DD + k] = lo;
    }
}

// ---------------- activation bf16 split ---------------------------------------
__global__ void split_a(const float* __restrict__ x) {
    int i = blockIdx.x * blockDim.x + threadIdx.x;   // over NN*DD/4
    if (i >= NN*DD/4) return;
    float4 v = ((const float4*)x)[i];
    __nv_bfloat16 h0 = __float2bfloat16_rn(v.x), h1 = __float2bfloat16_rn(v.y),
                  h2 = __float2bfloat16_rn(v.z), h3 = __float2bfloat16_rn(v.w);
    __nv_bfloat16 l0 = __float2bfloat16_rn(v.x - __bfloat162float(h0));
    __nv_bfloat16 l1 = __float2bfloat16_rn(v.y - __bfloat162float(h1));
    __nv_bfloat16 l2 = __float2bfloat16_rn(v.z - __bfloat162float(h2));
    __nv_bfloat16 l3 = __float2bfloat16_rn(v.w - __bfloat162float(h3));
    __nv_bfloat162* oh = (__nv_bfloat162*)g_Ah;
    __nv_bfloat162* ol = (__nv_bfloat162*)g_Al;
    oh[i*2]   = __halves2bfloat162(h0, h1);
    oh[i*2+1] = __halves2bfloat162(h2, h3);
    ol[i*2]   = __halves2bfloat162(l0, l1);
    ol[i*2+1] = __halves2bfloat162(l2, l3);
}

// ---------------- bf16 mma.sync GEMM: C = A[M,512] @ W^T (+res) ---------------
// 128x128 CTA tile, KC=32, 256 threads (8 warps 2x4), warp tile 64x32.
// 3-term bf16 split (ah*bh + ah*bl + al*bh), m16n8k16, term-outermost ordering.
// Padded smem rows (80B) -> conflict-free fragment LDS. Double-buffered,
// register-staged global fetch overlapping mma.
#define KC  32
#define RPB 80              // padded row bytes (40 bf16)
#define MTB (128*RPB)       // 10240 B per matrix tile
#define BUFB (4*MTB)        // AH AL BH BL = 40960 B
#define GSM (2*BUFB)        // 81920 B dynamic smem

#define LD32(base, m, k) (*(const uint32_t*)((base) + (m)*RPB + (k)*2))

__device__ __forceinline__ void mma16(float* c, const uint32_t* a, const uint32_t* b) {
    asm("mma.sync.aligned.m16n8k16.row.col.f32.bf16.bf16.f32 "
        "{%0,%1,%2,%3}, {%4,%5,%6,%7}, {%8,%9}, {%0,%1,%2,%3};"
        : "+f"(c[0]), "+f"(c[1]), "+f"(c[2]), "+f"(c[3])
        : "r"(a[0]), "r"(a[1]), "r"(a[2]), "r"(a[3]), "r"(b[0]), "r"(b[1]));
}

template <bool RES>
__device__ __forceinline__ void bf16_gemm_body(
    const __nv_bfloat16* __restrict__ Ah, const __nv_bfloat16* __restrict__ Al,
    const __nv_bfloat16* __restrict__ Bh, const __nv_bfloat16* __restrict__ Bl,
    float* __restrict__ C, const float* __restrict__ res, int bx, int by)
{
    extern __shared__ char sm[];
    const int tid  = threadIdx.x;
    const int w    = tid >> 5, lane = tid & 31;
    const int gid  = lane >> 2, tig = lane & 3;
    const int wm   = (w & 1) * 64, wn = (w >> 1) * 32;

    // staging coords: row = tid>>2 (0..63, +64), q = tid&3 (16B chunk)
    const int sr = tid >> 2, sq = tid & 3;

    float acc[4][4][4];
    #pragma unroll
    for (int i = 0; i < 4; i++)
        #pragma unroll
        for (int j = 0; j < 4; j++) {
            acc[i][j][0] = 0.f; acc[i][j][1] = 0.f;
            acc[i][j][2] = 0.f; acc[i][j][3] = 0.f;
        }

    uint4 vah0, vah1, val0, val1, vbh0, vbh1, vbl0, vbl1;
    auto fetch = [&](int kc) {
        size_t a0 = (size_t)(by*128 + sr) * DD + kc + sq*8;
        size_t a1 = a0 + (size_t)64 * DD;
        size_t b0 = (size_t)(bx*128 + sr) * DD + kc + sq*8;
        size_t b1 = b0 + (size_t)64 * DD;
        vah0 = *(const uint4*)(Ah + a0);  vah1 = *(const uint4*)(Ah + a1);
        val0 = *(const uint4*)(Al + a0);  val1 = *(const uint4*)(Al + a1);
        vbh0 = *(const uint4*)(Bh + b0);  vbh1 = *(const uint4*)(Bh + b1);
        vbl0 = *(const uint4*)(Bl + b0);  vbl1 = *(const uint4*)(Bl + b1);
    };
    auto stage = [&](int buf) {
        char* p = sm + buf * BUFB;
        uint32_t o0 = sr*RPB + sq*16, o1 = (sr + 64)*RPB + sq*16;
        *(uint4*)(p + o0)        = vah0;  *(uint4*)(p + o1)        = vah1;
        *(uint4*)(p + MTB + o0)  = val0;  *(uint4*)(p + MTB + o1)  = val1;
        *(uint4*)(p + 2*MTB + o0) = vbh0; *(uint4*)(p + 2*MTB + o1) = vbh1;
        *(uint4*)(p + 3*MTB + o0) = vbl0; *(uint4*)(p + 3*MTB + o1) = vbl1;
    };
    auto compute = [&](int buf) {
        const char* pah = sm + buf * BUFB;
        const char* pal = pah + MTB;
        const char* pbh = pah + 2*MTB;
        const char* pbl = pah + 3*MTB;
        #pragma unroll
        for (int ks = 0; ks < 2; ks++) {
            const int kb = ks*16 + tig*2;
            uint32_t ah[4][4], al[4][4], bh[4][2], bl[4][2];
            #pragma unroll
            for (int mt = 0; mt < 4; mt++) {
                int m = wm + mt*16 + gid;
                ah[mt][0] = LD32(pah, m,   kb);   ah[mt][1] = LD32(pah, m+8, kb);
                ah[mt][2] = LD32(pah, m,   kb+8); ah[mt][3] = LD32(pah, m+8, kb+8);
                al[mt][0] = LD32(pal, m,   kb);   al[mt][1] = LD32(pal, m+8, kb);
                al[mt][2] = LD32(pal, m,   kb+8); al[mt][3] = LD32(pal, m+8, kb+8);
            }
            #pragma unroll
            for (int nt = 0; nt < 4; nt++) {
                int n = wn + nt*8 + gid;
                bh[nt][0] = LD32(pbh, n, kb);  bh[nt][1] = LD32(pbh, n, kb+8);
                bl[nt][0] = LD32(pbl, n, kb);  bl[nt][1] = LD32(pbl, n, kb+8);
            }
            // term-outermost: 16 independent accumulators between reuses
            #pragma unroll
            for (int mt = 0; mt < 4; mt++)
                #pragma unroll
                for (int nt = 0; nt < 4; nt++) mma16(acc[mt][nt], ah[mt], bh[nt]);
            #pragma unroll
            for (int mt = 0; mt < 4; mt++)
                #pragma unroll
                for (int nt = 0; nt < 4; nt++) mma16(acc[mt][nt], ah[mt], bl[nt]);
            #pragma unroll
            for (int mt = 0; mt < 4; mt++)
                #pragma unroll
                for (int nt = 0; nt < 4; nt++) mma16(acc[mt][nt], al[mt], bh[nt]);
        }
    };

    fetch(0);
    stage(0);
    __syncthreads();

    for (int kt = 0; kt < 512; kt += KC) {
        const int cur = (kt / KC) & 1;
        const bool more = (kt + KC) < 512;
        if (more) fetch(kt + KC);       // non-blocking LDGs overlap mma
        compute(cur);
        if (more) stage(cur ^ 1);
        __syncthreads();
    }

    // Epilogue: c0,c1 -> (row gid, cols 2tig..); c2,c3 -> row gid+8
    #pragma unroll
    for (int mt = 0; mt < 4; mt++) {
        #pragma unroll
        for (int nt = 0; nt < 4; nt++) {
            int r0 = by*128 + wm + mt*16 + gid;
            int cc = bx*128 + wn + nt*8 + tig*2;
            float2 v0 = make_float2(acc[mt][nt][0], acc[mt][nt][1]);
            float2 v1 = make_float2(acc[mt][nt][2], acc[mt][nt][3]);
            if (RES) {
                float2 q0 = *(const float2*)(res + (size_t)r0 * DD + cc);
                float2 q1 = *(const float2*)(res + (size_t)(r0+8) * DD + cc);
                v0.x += q0.x; v0.y += q0.y; v1.x += q1.x; v1.y += q1.y;
            }
            *(float2*)(C + (size_t)r0     * DD + cc) = v0;
            *(float2*)(C + (size_t)(r0+8) * DD + cc) = v1;
        }
    }
}

__global__ void __launch_bounds__(256)
qkv_mm(const __nv_bfloat16* __restrict__ Ah, const __nv_bfloat16* __restrict__ Al,
       const __nv_bfloat16* __restrict__ WhL, const __nv_bfloat16* __restrict__ WlL,
       float* __restrict__ Cq, float* __restrict__ Ck, float* __restrict__ Cv) {
    int z = blockIdx.z;
    const __nv_bfloat16* Bh = WhL + (size_t)z * DD * DD;
    const __nv_bfloat16* Bl = WlL + (size_t)z * DD * DD;
    float* C = (z == 0) ? Cq : (z == 1) ? Ck : Cv;
    bf16_gemm_body<false>(Ah, Al, Bh, Bl, C, nullptr, blockIdx.x, blockIdx.y);
}

__global__ void __launch_bounds__(256)
o_mm(const __nv_bfloat16* __restrict__ Ah, const __nv_bfloat16* __restrict__ Al,
     const __nv_bfloat16* __restrict__ Bh, const __nv_bfloat16* __restrict__ Bl,
     float* __restrict__ C, const float* __restrict__ res) {
    bf16_gemm_body<true>(Ah, Al, Bh, Bl, C, res, blockIdx.x, blockIdx.y);
}

// ---------------- edge pass 1: logits + segment max --------------------------
__global__ void edge_logits(const float* __restrict__ dre,
                            const float* __restrict__ dae,
                            const float* __restrict__ rpe) {
    int warp = (blockIdx.x * blockDim.x + threadIdx.x) >> 5;
    int lane = threadIdx.x & 31;
    int total = g_starts[NB];
    if (warp >= total) return;
    int e = warp;
    int src = g_src[e], tgt = g_tgt[e];
    int d0 = lane * 2;
    int dr = g_dr[e], da = g_da[e], rp = g_rp[e];
    const float2 drv = *(const float2*)(dre + dr*DKK + d0);
    const float2 dav = *(const float2*)(dae + da*DKK + d0);
    const float2 rpv = *(const float2*)(rpe + rp*DKK + d0);
    float r0 = drv.x + dav.x + rpv.x;
    float r1 = drv.y + dav.y + rpv.y;
    #pragma unroll
    for (int h = 0; h < HH; h++) {
        const float2 kk = *(const float2*)(g_K + (size_t)src*DD + h*DKK + d0);
        const float2 qq = *(const float2*)(g_Q + (size_t)tgt*DD + h*DKK + d0);
        float p = qq.x * (kk.x + r0) + qq.y * (kk.y + r1);
        #pragma unroll
        for (int off = 16; off; off >>= 1) p += __shfl_xor_sync(0xffffffffu, p, off);
        if (lane == 0) {
            float lg = p * 0.125f;
            g_ev[(size_t)e*HH + h] = lg;
            atomicMax(&g_mkey[tgt*HH + h], fkey(lg));
        }
    }
}

// ---------------- edge pass 2: exp + segment sum -----------------------------
__global__ void edge_expsum() {
    int idx = blockIdx.x * blockDim.x + threadIdx.x;
    int total = g_starts[NB];
    if (idx >= total * HH) return;
    int e = idx >> 3;
    int h = idx & 7;
    int tgt = g_tgt[e];
    float m = funkey(g_mkey[tgt*HH + h]);
    float ev = __expf(g_ev[idx] - m);
    g_ev[idx] = ev;
    atomicAdd(&g_denom[tgt*HH + h], ev);
}

// ---------------- edge pass 3: alpha + scatter aggregation -------------------
__global__ void edge_aggregate(const float* __restrict__ dre,
                               const float* __restrict__ dae,
                               const float* __restrict__ rpe,
                               float* __restrict__ alpha_out) {
    int warp = (blockIdx.x * blockDim.x + threadIdx.x) >> 5;
    int lane = threadIdx.x & 31;
    int total = g_starts[NB];
    if (warp >= total) return;
    int e = warp;
    int src = g_src[e], tgt = g_tgt[e];
    int d0 = lane * 2;
    int dr = g_dr[e], da = g_da[e], rp = g_rp[e];
    const float2 drv = *(const float2*)(dre + dr*DKK + d0);
    const float2 dav = *(const float2*)(dae + da*DKK + d0);
    const float2 rpv = *(const float2*)(rpe + rp*DKK + d0);
    float r0 = drv.x + dav.x + rpv.x;
    float r1 = drv.y + dav.y + rpv.y;

    float al[HH];
    #pragma unroll
    for (int h = 0; h < HH; h++)
        al[h] = g_ev[(size_t)e*HH + h] / (g_denom[tgt*HH + h] + 1e-9f);
    if (lane < HH) alpha_out[(size_t)e*HH + lane] = al[lane];

    #pragma unroll
    for (int h = 0; h < HH; h++) {
        const float2 vv = *(const float2*)(g_V + (size_t)src*DD + h*DKK + d0);
        atomicAdd(&g_AGG[(size_t)tgt*DD + h*DKK + d0],     al[h] * (vv.x + r0));
        atomicAdd(&g_AGG[(size_t)tgt*DD + h*DKK + d0 + 1], al[h] * (vv.y + r1));
    }
}

// ---------------- LayerNorm (+ fused bf16 split of output when EMIT) ----------
__global__ void ln_kernel(const float* __restrict__ x,
                          const float* __restrict__ scale,
                          const float* __restrict__ bias,
                          float* __restrict__ out, int do_relu, int emit_split) {
    int row = blockIdx.x;
    const float* xr = x + (size_t)row * DD;
    int t = threadIdx.x;
    float v[4];
    float s = 0.f;
    #pragma unroll
    for (int i = 0; i < 4; i++) { v[i] = xr[t + i*128]; s += v[i]; }
    __shared__ float red[4];
    #pragma unroll
    for (int off = 16; off; off >>= 1) s += __shfl_xor_sync(0xffffffffu, s, off);
    if ((t & 31) == 0) red[t >> 5] = s;
    __syncthreads();
    s = red[0] + red[1] + red[2] + red[3];
    float mu = s * (1.f / DD);
    float vs = 0.f;
    #pragma unroll
    for (int i = 0; i < 4; i++) { float d = v[i] - mu; vs += d*d; }
    __syncthreads();
    #pragma unroll
    for (int off = 16; off; off >>= 1) vs += __shfl_xor_sync(0xffffffffu, vs, off);
    if ((t & 31) == 0) red[t >> 5] = vs;
    __syncthreads();
    vs = red[0] + red[1] + red[2] + red[3];
    float rstd = rsqrtf(vs * (1.f / DD) + 1e-5f);
    float* orow = out + (size_t)row * DD;
    #pragma unroll
    for (int i = 0; i < 4; i++) {
        int d = t + i*128;
        float y = (v[i] - mu) * rstd * scale[d] + bias[d];
        if (do_relu) y = fmaxf(y, 0.f);
        orow[d] = y;
        if (emit_split) {
            __nv_bfloat16 hh = __float2bfloat16_rn(y);
            g_Ah[(size_t)row*DD + d] = hh;
            g_Al[(size_t)row*DD + d] = __float2bfloat16_rn(y - __bfloat162float(hh));
        }
    }
}

// ---------------- host orchestration -----------------------------------------
extern "C" void kernel_launch(void* const* d_in, const int* in_sizes, int n_in,
                              void* d_out, int out_size) {
    const float* inp        = (const float*)d_in[0];
    const int*   edge_len   = (const int*)  d_in[2];
    const int*   edge_index = (const int*)  d_in[3];
    const int*   rp_in      = (const int*)  d_in[4];
    const int*   dr_in      = (const int*)  d_in[6];
    const int*   da_in      = (const int*)  d_in[7];
    const float* Wq         = (const float*)d_in[14];
    const float* Wk         = (const float*)d_in[15];
    const float* Wv         = (const float*)d_in[16];
    const float* Wo         = (const float*)d_in[17];
    const float* dre        = (const float*)d_in[18];
    const float* dae        = (const float*)d_in[19];
    const float* rpe        = (const float*)d_in[20];
    const float* ln_s       = (const float*)d_in[21];
    const float* ln_b       = (const float*)d_in[22];

    float* out   = (float*)d_out;
    float* reps  = out;                             // [L, N, D]
    float* attns = out + (size_t)LL * NN * DD;      // [L, BE, H]

    float *Qp, *Kp, *Vp, *AGGp, *LINp;
    __nv_bfloat16 *Ahp, *Alp, *Whp, *Wlp;
    cudaGetSymbolAddress((void**)&Qp,   g_Q);
    cudaGetSymbolAddress((void**)&Kp,   g_K);
    cudaGetSymbolAddress((void**)&Vp,   g_V);
    cudaGetSymbolAddress((void**)&AGGp, g_AGG);
    cudaGetSymbolAddress((void**)&LINp, g_LIN);
    cudaGetSymbolAddress((void**)&Ahp,  g_Ah);
    cudaGetSymbolAddress((void**)&Alp,  g_Al);
    cudaGetSymbolAddress((void**)&Whp,  g_Wh);
    cudaGetSymbolAddress((void**)&Wlp,  g_Wl);

    cudaFuncSetAttribute(qkv_mm, cudaFuncAttributeMaxDynamicSharedMemorySize, GSM);
    cudaFuncSetAttribute(o_mm,   cudaFuncAttributeMaxDynamicSharedMemorySize, GSM);

    prep_kernel<<<1, 32>>>(edge_len);
    flatten_kernel<<<(NB*EE + 255)/256, 256>>>(edge_len, edge_index, dr_in, da_in, rp_in);
    zero_f<<<(LL*BEE*HH + 255)/256, 256>>>(attns, LL*BEE*HH);
    split_w<<<dim3(16, 16, 8), dim3(32, 8)>>>(Wq, Wk, Wv, Wo);

    const int splitA_grid = (NN*DD/4 + 255)/256;
    for (int l = 0; l < LL; l++) {
        // activations for QKV GEMM: layer 0 splits the input; later layers'
        // splits were emitted by the previous ln_kernel.
        if (l == 0) split_a<<<splitA_grid, 256>>>(inp);
        qkv_mm<<<dim3(4, 128, 3), 256, GSM>>>(Ahp, Alp,
            Whp + (size_t)l*4*DD*DD, Wlp + (size_t)l*4*DD*DD, Qp, Kp, Vp);

        layer_init<<<(NN*DD + 255)/256, 256>>>();

        const float* drl = dre + (size_t)l * 50 * DKK;
        const float* dal = dae + (size_t)l * 3  * DKK;
        const float* rpl = rpe + (size_t)l * 21 * DKK;

        edge_logits<<<BEE/8, 256>>>(drl, dal, rpl);
        edge_expsum<<<(BEE*HH + 255)/256, 256>>>();
        edge_aggregate<<<BEE/8, 256>>>(drl, dal, rpl, attns + (size_t)l * BEE * HH);

        split_a<<<splitA_grid, 256>>>(AGGp);
        const float* resid = (l == 0) ? inp : (reps + (size_t)(l-1) * NN * DD);
        o_mm<<<dim3(4, 128, 1), 256, GSM>>>(Ahp, Alp,
            Whp + (size_t)(l*4+3)*DD*DD, Wlp + (size_t)(l*4+3)*DD*DD, LINp, resid);

        float* rep_l = reps + (size_t)l * NN * DD;
        ln_kernel<<<NN, 128>>>(LINp, ln_s + (size_t)l * DD, ln_b + (size_t)l * DD,
                               rep_l, (l < LL - 1) ? 1 : 0, (l < LL - 1) ? 1 : 0);
    }
}

// round 13
// speedup vs baseline: 2.0190x; 1.0384x over previous
#include <cuda_runtime.h>
#include <cuda_bf16.h>
#include <cstdint>

// Problem constants
#define NB 16           // B
#define SS 1024         // S
#define EE 8192         // E
#define DD 512          // D  (= H*DK)
#define HH 8            // H
#define DKK 64          // DK
#define LL 2            // L
#define NN (NB*SS)      // 16384 nodes
#define BEE (NB*EE)     // 131072 edges (padded)

// ---------------- scratch (device globals; no allocation allowed) -------------
__device__ float g_Q[NN*DD];
__device__ float g_K[NN*DD];
__device__ float g_V[NN*DD];
__device__ float g_AGG[NN*DD];
__device__ float g_LIN[NN*DD];
__device__ __nv_bfloat16 g_Ah[NN*DD];     // activation hi split
__device__ __nv_bfloat16 g_Al[NN*DD];     // activation lo split
__device__ __nv_bfloat16 g_Wh[8*DD*DD];   // weights, transposed [n][k], hi
__device__ __nv_bfloat16 g_Wl[8*DD*DD];   // weights, transposed [n][k], lo
__device__ int   g_src[BEE];
__device__ int   g_tgt[BEE];
__device__ int   g_dr[BEE];
__device__ int   g_da[BEE];
__device__ int   g_rp[BEE];
__device__ float g_ev[BEE*HH];            // per-edge per-head logits
__device__ int   g_starts[NB+1];
// CSR by target node
__device__ int   g_deg[NN];
__device__ int   g_cur[NN];
__device__ int   g_rowptr[NN+1];
__device__ int   g_eid[BEE];

// ---------------- prep: exclusive scan of edge_len ----------------------------
__global__ void prep_kernel(const int* __restrict__ edge_len) {
    if (threadIdx.x == 0 && blockIdx.x == 0) {
        int s = 0;
        for (int b = 0; b < NB; b++) { g_starts[b] = s; s += edge_len[b]; }
        g_starts[NB] = s;
    }
}

// ---------------- zero aux (deg/cur) ------------------------------------------
__global__ void zero_aux() {
    int i = blockIdx.x * blockDim.x + threadIdx.x;
    if (i < NN) { g_deg[i] = 0; g_cur[i] = 0; }
}

// ---------------- flatten ragged edges (+ degree histogram) -------------------
__global__ void flatten_kernel(const int* __restrict__ edge_len,
                               const int* __restrict__ edge_index,
                               const int* __restrict__ drl,
                               const int* __restrict__ dac,
                               const int* __restrict__ rpp) {
    int i = blockIdx.x * blockDim.x + threadIdx.x;
    if (i >= NB*EE) return;
    int b = i / EE, e = i % EE;
    if (e < edge_len[b]) {
        int fp = g_starts[b] + e;
        int tgt = edge_index[(size_t)i*2 + 1] + b*SS;
        g_src[fp] = edge_index[(size_t)i*2 + 0] + b*SS;
        g_tgt[fp] = tgt;
        g_dr[fp]  = drl[i];
        g_da[fp]  = dac[i];
        g_rp[fp]  = rpp[i];
        atomicAdd(&g_deg[tgt], 1);
    }
}

// ---------------- exclusive scan of g_deg -> g_rowptr (1 block, 512 thr) ------
__global__ void scan_deg() {
    __shared__ int warpsum[16];
    int t = threadIdx.x;                 // 0..511
    int base = t * 32;
    int local[32];
    int s = 0;
    #pragma unroll
    for (int i = 0; i < 32; i++) { local[i] = s; s += g_deg[base + i]; }
    int lane = t & 31, wid = t >> 5;
    int v = s;
    #pragma unroll
    for (int off = 1; off < 32; off <<= 1) {
        int n = __shfl_up_sync(0xffffffffu, v, off);
        if (lane >= off) v += n;
    }
    if (lane == 31) warpsum[wid] = v;
    __syncthreads();
    if (wid == 0) {
        int w = (lane < 16) ? warpsum[lane] : 0;
        #pragma unroll
        for (int off = 1; off < 16; off <<= 1) {
            int n = __shfl_up_sync(0xffffffffu, w, off);
            if (lane >= off) w += n;
        }
        if (lane < 16) warpsum[lane] = w;
    }
    __syncthreads();
    int excl = v - s + (wid ? warpsum[wid - 1] : 0);
    #pragma unroll
    for (int i = 0; i < 32; i++) g_rowptr[base + i] = excl + local[i];
    if (t == 511) g_rowptr[NN] = excl + s;
}

// ---------------- scatter edge ids into CSR order -----------------------------
__global__ void scatter_csr() {
    int i = blockIdx.x * blockDim.x + threadIdx.x;
    if (i >= g_rowptr[NN]) return;
    int t = g_tgt[i];
    int pos = g_rowptr[t] + atomicAdd(&g_cur[t], 1);
    g_eid[pos] = i;
}

// ---------------- zero fill (attn output padding) ------------------------------
__global__ void zero_f(float* __restrict__ p, int n) {
    int i = blockIdx.x * blockDim.x + threadIdx.x;
    if (i < n) p[i] = 0.f;
}

// ---------------- weight transpose + bf16 split -------------------------------
// W[l][k][n] -> g_Wh/g_Wl[g][n][k], g = l*4 + {q,k,v,o}
__global__ void split_w(const float* __restrict__ Wq, const float* __restrict__ Wk,
                        const float* __restrict__ Wv, const float* __restrict__ Wo) {
    __shared__ float t[32][33];
    int g = blockIdx.z, l = g >> 2, w = g & 3;
    const float* W = (w==0?Wq:w==1?Wk:w==2?Wv:Wo) + (size_t)l*DD*DD;
    __nv_bfloat16* oh = g_Wh + (size_t)g*DD*DD;
    __nv_bfloat16* ol = g_Wl + (size_t)g*DD*DD;
    int k0 = blockIdx.x*32, n0 = blockIdx.y*32;
    int tx = threadIdx.x, ty = threadIdx.y;
    #pragma unroll
    for (int i = 0; i < 4; i++)
        t[ty + i*8][tx] = W[(size_t)(k0 + ty + i*8)*DD + n0 + tx];
    __syncthreads();
    #pragma unroll
    for (int i = 0; i < 4; i++) {
        int n = n0 + ty + i*8, k = k0 + tx;
        float x = t[tx][ty + i*8];
        __nv_bfloat16 h = __float2bfloat16_rn(x);
        __nv_bfloat16 lo = __float2bfloat16_rn(x - __bfloat162float(h));
        oh[(size_t)n*DD + k] = h;
        ol[(size_t)n*DD + k] = lo;
    }
}

// ---------------- activation bf16 split ---------------------------------------
__global__ void split_a(const float* __restrict__ x) {
    int i = blockIdx.x * blockDim.x + threadIdx.x;   // over NN*DD/4
    if (i >= NN*DD/4) return;
    float4 v = ((const float4*)x)[i];
    __nv_bfloat16 h0 = __float2bfloat16_rn(v.x), h1 = __float2bfloat16_rn(v.y),
                  h2 = __float2bfloat16_rn(v.z), h3 = __float2bfloat16_rn(v.w);
    __nv_bfloat16 l0 = __float2bfloat16_rn(v.x - __bfloat162float(h0));
    __nv_bfloat16 l1 = __float2bfloat16_rn(v.y - __bfloat162float(h1));
    __nv_bfloat16 l2 = __float2bfloat16_rn(v.z - __bfloat162float(h2));
    __nv_bfloat16 l3 = __float2bfloat16_rn(v.w - __bfloat162float(h3));
    __nv_bfloat162* oh = (__nv_bfloat162*)g_Ah;
    __nv_bfloat162* ol = (__nv_bfloat162*)g_Al;
    oh[i*2]   = __halves2bfloat162(h0, h1);
    oh[i*2+1] = __halves2bfloat162(h2, h3);
    ol[i*2]   = __halves2bfloat162(l0, l1);
    ol[i*2+1] = __halves2bfloat162(l2, l3);
}

// ---------------- bf16 mma.sync GEMM: C = A[M,512] @ W^T (+res) ---------------
// (unchanged from R11 — measured as part of the 1131us win)
#define KC  32
#define RPB 80
#define MTB (128*RPB)
#define BUFB (4*MTB)
#define GSM (2*BUFB)

#define LD32(base, m, k) (*(const uint32_t*)((base) + (m)*RPB + (k)*2))

__device__ __forceinline__ void mma16(float* c, const uint32_t* a, const uint32_t* b) {
    asm("mma.sync.aligned.m16n8k16.row.col.f32.bf16.bf16.f32 "
        "{%0,%1,%2,%3}, {%4,%5,%6,%7}, {%8,%9}, {%0,%1,%2,%3};"
        : "+f"(c[0]), "+f"(c[1]), "+f"(c[2]), "+f"(c[3])
        : "r"(a[0]), "r"(a[1]), "r"(a[2]), "r"(a[3]), "r"(b[0]), "r"(b[1]));
}

template <bool RES>
__device__ __forceinline__ void bf16_gemm_body(
    const __nv_bfloat16* __restrict__ Ah, const __nv_bfloat16* __restrict__ Al,
    const __nv_bfloat16* __restrict__ Bh, const __nv_bfloat16* __restrict__ Bl,
    float* __restrict__ C, const float* __restrict__ res, int bx, int by)
{
    extern __shared__ char sm[];
    const int tid  = threadIdx.x;
    const int w    = tid >> 5, lane = tid & 31;
    const int gid  = lane >> 2, tig = lane & 3;
    const int wm   = (w & 1) * 64, wn = (w >> 1) * 32;
    const int sr = tid >> 2, sq = tid & 3;

    float acc[4][4][4];
    #pragma unroll
    for (int i = 0; i < 4; i++)
        #pragma unroll
        for (int j = 0; j < 4; j++) {
            acc[i][j][0] = 0.f; acc[i][j][1] = 0.f;
            acc[i][j][2] = 0.f; acc[i][j][3] = 0.f;
        }

    uint4 vah0, vah1, val0, val1, vbh0, vbh1, vbl0, vbl1;
    auto fetch = [&](int kc) {
        size_t a0 = (size_t)(by*128 + sr) * DD + kc + sq*8;
        size_t a1 = a0 + (size_t)64 * DD;
        size_t b0 = (size_t)(bx*128 + sr) * DD + kc + sq*8;
        size_t b1 = b0 + (size_t)64 * DD;
        vah0 = *(const uint4*)(Ah + a0);  vah1 = *(const uint4*)(Ah + a1);
        val0 = *(const uint4*)(Al + a0);  val1 = *(const uint4*)(Al + a1);
        vbh0 = *(const uint4*)(Bh + b0);  vbh1 = *(const uint4*)(Bh + b1);
        vbl0 = *(const uint4*)(Bl + b0);  vbl1 = *(const uint4*)(Bl + b1);
    };
    auto stage = [&](int buf) {
        char* p = sm + buf * BUFB;
        uint32_t o0 = sr*RPB + sq*16, o1 = (sr + 64)*RPB + sq*16;
        *(uint4*)(p + o0)        = vah0;  *(uint4*)(p + o1)        = vah1;
        *(uint4*)(p + MTB + o0)  = val0;  *(uint4*)(p + MTB + o1)  = val1;
        *(uint4*)(p + 2*MTB + o0) = vbh0; *(uint4*)(p + 2*MTB + o1) = vbh1;
        *(uint4*)(p + 3*MTB + o0) = vbl0; *(uint4*)(p + 3*MTB + o1) = vbl1;
    };
    auto compute = [&](int buf) {
        const char* pah = sm + buf * BUFB;
        const char* pal = pah + MTB;
        const char* pbh = pah + 2*MTB;
        const char* pbl = pah + 3*MTB;
        #pragma unroll
        for (int ks = 0; ks < 2; ks++) {
            const int kb = ks*16 + tig*2;
            uint32_t ah[4][4], al[4][4], bh[4][2], bl[4][2];
            #pragma unroll
            for (int mt = 0; mt < 4; mt++) {
                int m = wm + mt*16 + gid;
                ah[mt][0] = LD32(pah, m,   kb);   ah[mt][1] = LD32(pah, m+8, kb);
                ah[mt][2] = LD32(pah, m,   kb+8); ah[mt][3] = LD32(pah, m+8, kb+8);
                al[mt][0] = LD32(pal, m,   kb);   al[mt][1] = LD32(pal, m+8, kb);
                al[mt][2] = LD32(pal, m,   kb+8); al[mt][3] = LD32(pal, m+8, kb+8);
            }
            #pragma unroll
            for (int nt = 0; nt < 4; nt++) {
                int n = wn + nt*8 + gid;
                bh[nt][0] = LD32(pbh, n, kb);  bh[nt][1] = LD32(pbh, n, kb+8);
                bl[nt][0] = LD32(pbl, n, kb);  bl[nt][1] = LD32(pbl, n, kb+8);
            }
            #pragma unroll
            for (int mt = 0; mt < 4; mt++)
                #pragma unroll
                for (int nt = 0; nt < 4; nt++) mma16(acc[mt][nt], ah[mt], bh[nt]);
            #pragma unroll
            for (int mt = 0; mt < 4; mt++)
                #pragma unroll
                for (int nt = 0; nt < 4; nt++) mma16(acc[mt][nt], ah[mt], bl[nt]);
            #pragma unroll
            for (int mt = 0; mt < 4; mt++)
                #pragma unroll
                for (int nt = 0; nt < 4; nt++) mma16(acc[mt][nt], al[mt], bh[nt]);
        }
    };

    fetch(0);
    stage(0);
    __syncthreads();

    for (int kt = 0; kt < 512; kt += KC) {
        const int cur = (kt / KC) & 1;
        const bool more = (kt + KC) < 512;
        if (more) fetch(kt + KC);
        compute(cur);
        if (more) stage(cur ^ 1);
        __syncthreads();
    }

    #pragma unroll
    for (int mt = 0; mt < 4; mt++) {
        #pragma unroll
        for (int nt = 0; nt < 4; nt++) {
            int r0 = by*128 + wm + mt*16 + gid;
            int cc = bx*128 + wn + nt*8 + tig*2;
            float2 v0 = make_float2(acc[mt][nt][0], acc[mt][nt][1]);
            float2 v1 = make_float2(acc[mt][nt][2], acc[mt][nt][3]);
            if (RES) {
                float2 q0 = *(const float2*)(res + (size_t)r0 * DD + cc);
                float2 q1 = *(const float2*)(res + (size_t)(r0+8) * DD + cc);
                v0.x += q0.x; v0.y += q0.y; v1.x += q1.x; v1.y += q1.y;
            }
            *(float2*)(C + (size_t)r0     * DD + cc) = v0;
            *(float2*)(C + (size_t)(r0+8) * DD + cc) = v1;
        }
    }
}

__global__ void __launch_bounds__(256)
qkv_mm(const __nv_bfloat16* __restrict__ Ah, const __nv_bfloat16* __restrict__ Al,
       const __nv_bfloat16* __restrict__ WhL, const __nv_bfloat16* __restrict__ WlL,
       float* __restrict__ Cq, float* __restrict__ Ck, float* __restrict__ Cv) {
    int z = blockIdx.z;
    const __nv_bfloat16* Bh = WhL + (size_t)z * DD * DD;
    const __nv_bfloat16* Bl = WlL + (size_t)z * DD * DD;
    float* C = (z == 0) ? Cq : (z == 1) ? Ck : Cv;
    bf16_gemm_body<false>(Ah, Al, Bh, Bl, C, nullptr, blockIdx.x, blockIdx.y);
}

__global__ void __launch_bounds__(256)
o_mm(const __nv_bfloat16* __restrict__ Ah, const __nv_bfloat16* __restrict__ Al,
     const __nv_bfloat16* __restrict__ Bh, const __nv_bfloat16* __restrict__ Bl,
     float* __restrict__ C, const float* __restrict__ res) {
    bf16_gemm_body<true>(Ah, Al, Bh, Bl, C, res, blockIdx.x, blockIdx.y);
}

// ---------------- edge pass 1: logits only (no atomics) -----------------------
__global__ void edge_logits(const float* __restrict__ dre,
                            const float* __restrict__ dae,
                            const float* __restrict__ rpe) {
    int warp = (blockIdx.x * blockDim.x + threadIdx.x) >> 5;
    int lane = threadIdx.x & 31;
    int total = g_starts[NB];
    if (warp >= total) return;
    int e = warp;
    int src = g_src[e], tgt = g_tgt[e];
    int d0 = lane * 2;
    int dr = g_dr[e], da = g_da[e], rp = g_rp[e];
    const float2 drv = *(const float2*)(dre + dr*DKK + d0);
    const float2 dav = *(const float2*)(dae + da*DKK + d0);
    const float2 rpv = *(const float2*)(rpe + rp*DKK + d0);
    float r0 = drv.x + dav.x + rpv.x;
    float r1 = drv.y + dav.y + rpv.y;
    #pragma unroll
    for (int h = 0; h < HH; h++) {
        const float2 kk = *(const float2*)(g_K + (size_t)src*DD + h*DKK + d0);
        const float2 qq = *(const float2*)(g_Q + (size_t)tgt*DD + h*DKK + d0);
        float p = qq.x * (kk.x + r0) + qq.y * (kk.y + r1);
        #pragma unroll
        for (int off = 16; off; off >>= 1) p += __shfl_xor_sync(0xffffffffu, p, off);
        if (lane == 0) g_ev[(size_t)e*HH + h] = p * 0.125f;  // 1/sqrt(64)
    }
}

// ---------------- edge pass 2 (fused): softmax + aggregate, warp per node -----
// CSR walk: per-head max, exp-sum, alpha write, and assignment (no atomics,
// no zero-init) of agg = sum alpha*(v[src]+rel).
__global__ void node_attn(const float* __restrict__ dre,
                          const float* __restrict__ dae,
                          const float* __restrict__ rpe,
                          float* __restrict__ alpha_out) {
    int node = (blockIdx.x * blockDim.x + threadIdx.x) >> 5;
    if (node >= NN) return;
    int lane = threadIdx.x & 31;
    int r0 = g_rowptr[node], r1 = g_rowptr[node+1];
    int d0 = lane * 2;

    float m[HH];
    #pragma unroll
    for (int h = 0; h < HH; h++) m[h] = -1e30f;
    for (int i = r0; i < r1; i++) {
        int e = g_eid[i];
        #pragma unroll
        for (int h = 0; h < HH; h++) m[h] = fmaxf(m[h], g_ev[(size_t)e*HH + h]);
    }
    float s[HH];
    #pragma unroll
    for (int h = 0; h < HH; h++) s[h] = 0.f;
    for (int i = r0; i < r1; i++) {
        int e = g_eid[i];
        #pragma unroll
        for (int h = 0; h < HH; h++) s[h] += __expf(g_ev[(size_t)e*HH + h] - m[h]);
    }
    float inv[HH];
    #pragma unroll
    for (int h = 0; h < HH; h++) inv[h] = 1.f / (s[h] + 1e-9f);

    float acc[2*HH];
    #pragma unroll
    for (int i = 0; i < 2*HH; i++) acc[i] = 0.f;

    for (int i = r0; i < r1; i++) {
        int e = g_eid[i];
        int src = g_src[e];
        int dr = g_dr[e], da = g_da[e], rp = g_rp[e];
        const float2 drv = *(const float2*)(dre + dr*DKK + d0);
        const float2 dav = *(const float2*)(dae + da*DKK + d0);
        const float2 rpv = *(const float2*)(rpe + rp*DKK + d0);
        float rr0 = drv.x + dav.x + rpv.x;
        float rr1 = drv.y + dav.y + rpv.y;
        float a[HH];
        #pragma unroll
        for (int h = 0; h < HH; h++)
            a[h] = __expf(g_ev[(size_t)e*HH + h] - m[h]) * inv[h];
        // alpha write: lane h writes a[h] (static unrolled select, no spill)
        float av = a[0];
        #pragma unroll
        for (int h = 1; h < HH; h++) if (lane == h) av = a[h];
        if (lane < HH) alpha_out[(size_t)e*HH + lane] = av;
        #pragma unroll
        for (int h = 0; h < HH; h++) {
            const float2 vv = *(const float2*)(g_V + (size_t)src*DD + h*DKK + d0);
            acc[2*h]   += a[h] * (vv.x + rr0);
            acc[2*h+1] += a[h] * (vv.y + rr1);
        }
    }
    #pragma unroll
    for (int h = 0; h < HH; h++)
        *(float2*)(g_AGG + (size_t)node*DD + h*DKK + d0) =
            make_float2(acc[2*h], acc[2*h+1]);
}

// ---------------- LayerNorm (+ fused bf16 split of output when EMIT) ----------
__global__ void ln_kernel(const float* __restrict__ x,
                          const float* __restrict__ scale,
                          const float* __restrict__ bias,
                          float* __restrict__ out, int do_relu, int emit_split) {
    int row = blockIdx.x;
    const float* xr = x + (size_t)row * DD;
    int t = threadIdx.x;
    float v[4];
    float s = 0.f;
    #pragma unroll
    for (int i = 0; i < 4; i++) { v[i] = xr[t + i*128]; s += v[i]; }
    __shared__ float red[4];
    #pragma unroll
    for (int off = 16; off; off >>= 1) s += __shfl_xor_sync(0xffffffffu, s, off);
    if ((t & 31) == 0) red[t >> 5] = s;
    __syncthreads();
    s = red[0] + red[1] + red[2] + red[3];
    float mu = s * (1.f / DD);
    float vs = 0.f;
    #pragma unroll
    for (int i = 0; i < 4; i++) { float d = v[i] - mu; vs += d*d; }
    __syncthreads();
    #pragma unroll
    for (int off = 16; off; off >>= 1) vs += __shfl_xor_sync(0xffffffffu, vs, off);
    if ((t & 31) == 0) red[t >> 5] = vs;
    __syncthreads();
    vs = red[0] + red[1] + red[2] + red[3];
    float rstd = rsqrtf(vs * (1.f / DD) + 1e-5f);
    float* orow = out + (size_t)row * DD;
    #pragma unroll
    for (int i = 0; i < 4; i++) {
        int d = t + i*128;
        float y = (v[i] - mu) * rstd * scale[d] + bias[d];
        if (do_relu) y = fmaxf(y, 0.f);
        orow[d] = y;
        if (emit_split) {
            __nv_bfloat16 hh = __float2bfloat16_rn(y);
            g_Ah[(size_t)row*DD + d] = hh;
            g_Al[(size_t)row*DD + d] = __float2bfloat16_rn(y - __bfloat162float(hh));
        }
    }
}

// ---------------- host orchestration -----------------------------------------
extern "C" void kernel_launch(void* const* d_in, const int* in_sizes, int n_in,
                              void* d_out, int out_size) {
    const float* inp        = (const float*)d_in[0];
    const int*   edge_len   = (const int*)  d_in[2];
    const int*   edge_index = (const int*)  d_in[3];
    const int*   rp_in      = (const int*)  d_in[4];
    const int*   dr_in      = (const int*)  d_in[6];
    const int*   da_in      = (const int*)  d_in[7];
    const float* Wq         = (const float*)d_in[14];
    const float* Wk         = (const float*)d_in[15];
    const float* Wv         = (const float*)d_in[16];
    const float* Wo         = (const float*)d_in[17];
    const float* dre        = (const float*)d_in[18];
    const float* dae        = (const float*)d_in[19];
    const float* rpe        = (const float*)d_in[20];
    const float* ln_s       = (const float*)d_in[21];
    const float* ln_b       = (const float*)d_in[22];

    float* out   = (float*)d_out;
    float* reps  = out;                             // [L, N, D]
    float* attns = out + (size_t)LL * NN * DD;      // [L, BE, H]

    float *Qp, *Kp, *Vp, *AGGp, *LINp;
    __nv_bfloat16 *Ahp, *Alp, *Whp, *Wlp;
    cudaGetSymbolAddress((void**)&Qp,   g_Q);
    cudaGetSymbolAddress((void**)&Kp,   g_K);
    cudaGetSymbolAddress((void**)&Vp,   g_V);
    cudaGetSymbolAddress((void**)&AGGp, g_AGG);
    cudaGetSymbolAddress((void**)&LINp, g_LIN);
    cudaGetSymbolAddress((void**)&Ahp,  g_Ah);
    cudaGetSymbolAddress((void**)&Alp,  g_Al);
    cudaGetSymbolAddress((void**)&Whp,  g_Wh);
    cudaGetSymbolAddress((void**)&Wlp,  g_Wl);

    cudaFuncSetAttribute(qkv_mm, cudaFuncAttributeMaxDynamicSharedMemorySize, GSM);
    cudaFuncSetAttribute(o_mm,   cudaFuncAttributeMaxDynamicSharedMemorySize, GSM);

    prep_kernel<<<1, 32>>>(edge_len);
    zero_aux<<<(NN + 255)/256, 256>>>();
    flatten_kernel<<<(NB*EE + 255)/256, 256>>>(edge_len, edge_index, dr_in, da_in, rp_in);
    scan_deg<<<1, 512>>>();
    scatter_csr<<<(BEE + 255)/256, 256>>>();
    zero_f<<<(LL*BEE*HH + 255)/256, 256>>>(attns, LL*BEE*HH);
    split_w<<<dim3(16, 16, 8), dim3(32, 8)>>>(Wq, Wk, Wv, Wo);

    const int splitA_grid = (NN*DD/4 + 255)/256;
    for (int l = 0; l < LL; l++) {
        if (l == 0) split_a<<<splitA_grid, 256>>>(inp);
        qkv_mm<<<dim3(4, 128, 3), 256, GSM>>>(Ahp, Alp,
            Whp + (size_t)l*4*DD*DD, Wlp + (size_t)l*4*DD*DD, Qp, Kp, Vp);

        const float* drl = dre + (size_t)l * 50 * DKK;
        const float* dal = dae + (size_t)l * 3  * DKK;
        const float* rpl = rpe + (size_t)l * 21 * DKK;

        edge_logits<<<BEE/8, 256>>>(drl, dal, rpl);
        node_attn<<<(NN*32 + 255)/256, 256>>>(drl, dal, rpl,
                                              attns + (size_t)l * BEE * HH);

        split_a<<<splitA_grid, 256>>>(AGGp);
        const float* resid = (l == 0) ? inp : (reps + (size_t)(l-1) * NN * DD);
        o_mm<<<dim3(4, 128, 1), 256, GSM>>>(Ahp, Alp,
            Whp + (size_t)(l*4+3)*DD*DD, Wlp + (size_t)(l*4+3)*DD*DD, LINp, resid);

        float* rep_l = reps + (size_t)l * NN * DD;
        ln_kernel<<<NN, 128>>>(LINp, ln_s + (size_t)l * DD, ln_b + (size_t)l * DD,
                               rep_l, (l < LL - 1) ? 1 : 0, (l < LL - 1) ? 1 : 0);
    }
}

// round 17
// speedup vs baseline: 2.0689x; 1.0247x over previous
#include <cuda_runtime.h>
#include <cuda_bf16.h>
#include <cstdint>

// Problem constants
#define NB 16           // B
#define SS 1024         // S
#define EE 8192         // E
#define DD 512          // D  (= H*DK)
#define HH 8            // H
#define DKK 64          // DK
#define LL 2            // L
#define NN (NB*SS)      // 16384 nodes
#define BEE (NB*EE)     // 131072 edges (padded)

// ---------------- scratch (device globals; no allocation allowed) -------------
__device__ float g_Q[NN*DD];
__device__ float g_K[NN*DD];
__device__ float g_V[NN*DD];
__device__ float g_LIN[NN*DD];
__device__ __nv_bfloat16 g_Ah[NN*DD];     // activation hi split
__device__ __nv_bfloat16 g_Al[NN*DD];     // activation lo split
__device__ __nv_bfloat16 g_Wh[8*DD*DD];   // weights, transposed [n][k], hi
__device__ __nv_bfloat16 g_Wl[8*DD*DD];   // weights, transposed [n][k], lo
__device__ int   g_src[BEE];
__device__ int   g_tgt[BEE];
__device__ int   g_dr[BEE];
__device__ int   g_da[BEE];
__device__ int   g_rp[BEE];
__device__ float g_ev[BEE*HH];            // per-edge per-head logits
__device__ int   g_starts[NB+1];
// CSR by target node
__device__ __align__(16) int g_deg[NN];
__device__ int   g_cur[NN];
__device__ int   g_rowptr[NN+1];
__device__ int   g_eid[BEE];

// ---------------- prep: exclusive scan of edge_len ----------------------------
__global__ void prep_kernel(const int* __restrict__ edge_len) {
    if (threadIdx.x == 0 && blockIdx.x == 0) {
        int s = 0;
        for (int b = 0; b < NB; b++) { g_starts[b] = s; s += edge_len[b]; }
        g_starts[NB] = s;
    }
}

// ---------------- zero aux (deg/cur) ------------------------------------------
__global__ void zero_aux() {
    int i = blockIdx.x * blockDim.x + threadIdx.x;
    if (i < NN) { g_deg[i] = 0; g_cur[i] = 0; }
}

// ---------------- flatten ragged edges (+ degree histogram) -------------------
__global__ void flatten_kernel(const int* __restrict__ edge_len,
                               const int* __restrict__ edge_index,
                               const int* __restrict__ drl,
                               const int* __restrict__ dac,
                               const int* __restrict__ rpp) {
    int i = blockIdx.x * blockDim.x + threadIdx.x;
    if (i >= NB*EE) return;
    int b = i / EE, e = i % EE;
    if (e < edge_len[b]) {
        int fp = g_starts[b] + e;
        int tgt = edge_index[(size_t)i*2 + 1] + b*SS;
        g_src[fp] = edge_index[(size_t)i*2 + 0] + b*SS;
        g_tgt[fp] = tgt;
        g_dr[fp]  = drl[i];
        g_da[fp]  = dac[i];
        g_rp[fp]  = rpp[i];
        atomicAdd(&g_deg[tgt], 1);
    }
}

// ---------------- exclusive scan of g_deg -> g_rowptr (1 block, 1024 thr) -----
// 16 elems/thread via int4 loads; two-level shfl scan across 32 warps.
__global__ void scan_deg() {
    __shared__ int warpsum[32];
    int t = threadIdx.x;                 // 0..1023
    int base = t * 16;
    int4 q0 = *(const int4*)&g_deg[base];
    int4 q1 = *(const int4*)&g_deg[base + 4];
    int4 q2 = *(const int4*)&g_deg[base + 8];
    int4 q3 = *(const int4*)&g_deg[base + 12];
    int vals[16] = {q0.x,q0.y,q0.z,q0.w, q1.x,q1.y,q1.z,q1.w,
                    q2.x,q2.y,q2.z,q2.w, q3.x,q3.y,q3.z,q3.w};
    int local[16];
    int s = 0;
    #pragma unroll
    for (int i = 0; i < 16; i++) { local[i] = s; s += vals[i]; }
    int lane = t & 31, wid = t >> 5;
    int v = s;
    #pragma unroll
    for (int off = 1; off < 32; off <<= 1) {
        int n = __shfl_up_sync(0xffffffffu, v, off);
        if (lane >= off) v += n;
    }
    if (lane == 31) warpsum[wid] = v;
    __syncthreads();
    if (wid == 0) {
        int w = warpsum[lane];
        #pragma unroll
        for (int off = 1; off < 32; off <<= 1) {
            int n = __shfl_up_sync(0xffffffffu, w, off);
            if (lane >= off) w += n;
        }
        warpsum[lane] = w;
    }
    __syncthreads();
    int excl = v - s + (wid ? warpsum[wid - 1] : 0);
    #pragma unroll
    for (int i = 0; i < 16; i++) g_rowptr[base + i] = excl + local[i];
    if (t == 1023) g_rowptr[NN] = excl + s;
}

// ---------------- scatter edge ids into CSR order -----------------------------
__global__ void scatter_csr() {
    int i = blockIdx.x * blockDim.x + threadIdx.x;
    if (i >= g_rowptr[NN]) return;
    int t = g_tgt[i];
    int pos = g_rowptr[t] + atomicAdd(&g_cur[t], 1);
    g_eid[pos] = i;
}

// ---------------- zero fill (attn output padding) ------------------------------
__global__ void zero_f(float* __restrict__ p, int n) {
    int i = blockIdx.x * blockDim.x + threadIdx.x;
    if (i < n) p[i] = 0.f;
}

// ---------------- weight transpose + bf16 split -------------------------------
// W[l][k][n] -> g_Wh/g_Wl[g][n][k], g = l*4 + {q,k,v,o}
__global__ void split_w(const float* __restrict__ Wq, const float* __restrict__ Wk,
                        const float* __restrict__ Wv, const float* __restrict__ Wo) {
    __shared__ float t[32][33];
    int g = blockIdx.z, l = g >> 2, w = g & 3;
    const float* W = (w==0?Wq:w==1?Wk:w==2?Wv:Wo) + (size_t)l*DD*DD;
    __nv_bfloat16* oh = g_Wh + (size_t)g*DD*DD;
    __nv_bfloat16* ol = g_Wl + (size_t)g*DD*DD;
    int k0 = blockIdx.x*32, n0 = blockIdx.y*32;
    int tx = threadIdx.x, ty = threadIdx.y;
    #pragma unroll
    for (int i = 0; i < 4; i++)
        t[ty + i*8][tx] = W[(size_t)(k0 + ty + i*8)*DD + n0 + tx];
    __syncthreads();
    #pragma unroll
    for (int i = 0; i < 4; i++) {
        int n = n0 + ty + i*8, k = k0 + tx;
        float x = t[tx][ty + i*8];
        __nv_bfloat16 h = __float2bfloat16_rn(x);
        __nv_bfloat16 lo = __float2bfloat16_rn(x - __bfloat162float(h));
        oh[(size_t)n*DD + k] = h;
        ol[(size_t)n*DD + k] = lo;
    }
}

// ---------------- activation bf16 split (input layer only) --------------------
__global__ void split_a(const float* __restrict__ x) {
    int i = blockIdx.x * blockDim.x + threadIdx.x;   // over NN*DD/4
    if (i >= NN*DD/4) return;
    float4 v = ((const float4*)x)[i];
    __nv_bfloat16 h0 = __float2bfloat16_rn(v.x), h1 = __float2bfloat16_rn(v.y),
                  h2 = __float2bfloat16_rn(v.z), h3 = __float2bfloat16_rn(v.w);
    __nv_bfloat16 l0 = __float2bfloat16_rn(v.x - __bfloat162float(h0));
    __nv_bfloat16 l1 = __float2bfloat16_rn(v.y - __bfloat162float(h1));
    __nv_bfloat16 l2 = __float2bfloat16_rn(v.z - __bfloat162float(h2));
    __nv_bfloat16 l3 = __float2bfloat16_rn(v.w - __bfloat162float(h3));
    __nv_bfloat162* oh = (__nv_bfloat162*)g_Ah;
    __nv_bfloat162* ol = (__nv_bfloat162*)g_Al;
    oh[i*2]   = __halves2bfloat162(h0, h1);
    oh[i*2+1] = __halves2bfloat162(h2, h3);
    ol[i*2]   = __halves2bfloat162(l0, l1);
    ol[i*2+1] = __halves2bfloat162(l2, l3);
}

// ---------------- bf16 mma.sync GEMM: C = A[M,512] @ W^T (+res) ---------------
// (unchanged — measured as part of the 1131/1089us wins)
#define KC  32
#define RPB 80
#define MTB (128*RPB)
#define BUFB (4*MTB)
#define GSM (2*BUFB)

#define LD32(base, m, k) (*(const uint32_t*)((base) + (m)*RPB + (k)*2))

__device__ __forceinline__ void mma16(float* c, const uint32_t* a, const uint32_t* b) {
    asm("mma.sync.aligned.m16n8k16.row.col.f32.bf16.bf16.f32 "
        "{%0,%1,%2,%3}, {%4,%5,%6,%7}, {%8,%9}, {%0,%1,%2,%3};"
        : "+f"(c[0]), "+f"(c[1]), "+f"(c[2]), "+f"(c[3])
        : "r"(a[0]), "r"(a[1]), "r"(a[2]), "r"(a[3]), "r"(b[0]), "r"(b[1]));
}

template <bool RES>
__device__ __forceinline__ void bf16_gemm_body(
    const __nv_bfloat16* __restrict__ Ah, const __nv_bfloat16* __restrict__ Al,
    const __nv_bfloat16* __restrict__ Bh, const __nv_bfloat16* __restrict__ Bl,
    float* __restrict__ C, const float* __restrict__ res, int bx, int by)
{
    extern __shared__ char sm[];
    const int tid  = threadIdx.x;
    const int w    = tid >> 5, lane = tid & 31;
    const int gid  = lane >> 2, tig = lane & 3;
    const int wm   = (w & 1) * 64, wn = (w >> 1) * 32;
    const int sr = tid >> 2, sq = tid & 3;

    float acc[4][4][4];
    #pragma unroll
    for (int i = 0; i < 4; i++)
        #pragma unroll
        for (int j = 0; j < 4; j++) {
            acc[i][j][0] = 0.f; acc[i][j][1] = 0.f;
            acc[i][j][2] = 0.f; acc[i][j][3] = 0.f;
        }

    uint4 vah0, vah1, val0, val1, vbh0, vbh1, vbl0, vbl1;
    auto fetch = [&](int kc) {
        size_t a0 = (size_t)(by*128 + sr) * DD + kc + sq*8;
        size_t a1 = a0 + (size_t)64 * DD;
        size_t b0 = (size_t)(bx*128 + sr) * DD + kc + sq*8;
        size_t b1 = b0 + (size_t)64 * DD;
        vah0 = *(const uint4*)(Ah + a0);  vah1 = *(const uint4*)(Ah + a1);
        val0 = *(const uint4*)(Al + a0);  val1 = *(const uint4*)(Al + a1);
        vbh0 = *(const uint4*)(Bh + b0);  vbh1 = *(const uint4*)(Bh + b1);
        vbl0 = *(const uint4*)(Bl + b0);  vbl1 = *(const uint4*)(Bl + b1);
    };
    auto stage = [&](int buf) {
        char* p = sm + buf * BUFB;
        uint32_t o0 = sr*RPB + sq*16, o1 = (sr + 64)*RPB + sq*16;
        *(uint4*)(p + o0)        = vah0;  *(uint4*)(p + o1)        = vah1;
        *(uint4*)(p + MTB + o0)  = val0;  *(uint4*)(p + MTB + o1)  = val1;
        *(uint4*)(p + 2*MTB + o0) = vbh0; *(uint4*)(p + 2*MTB + o1) = vbh1;
        *(uint4*)(p + 3*MTB + o0) = vbl0; *(uint4*)(p + 3*MTB + o1) = vbl1;
    };
    auto compute = [&](int buf) {
        const char* pah = sm + buf * BUFB;
        const char* pal = pah + MTB;
        const char* pbh = pah + 2*MTB;
        const char* pbl = pah + 3*MTB;
        #pragma unroll
        for (int ks = 0; ks < 2; ks++) {
            const int kb = ks*16 + tig*2;
            uint32_t ah[4][4], al[4][4], bh[4][2], bl[4][2];
            #pragma unroll
            for (int mt = 0; mt < 4; mt++) {
                int m = wm + mt*16 + gid;
                ah[mt][0] = LD32(pah, m,   kb);   ah[mt][1] = LD32(pah, m+8, kb);
                ah[mt][2] = LD32(pah, m,   kb+8); ah[mt][3] = LD32(pah, m+8, kb+8);
                al[mt][0] = LD32(pal, m,   kb);   al[mt][1] = LD32(pal, m+8, kb);
                al[mt][2] = LD32(pal, m,   kb+8); al[mt][3] = LD32(pal, m+8, kb+8);
            }
            #pragma unroll
            for (int nt = 0; nt < 4; nt++) {
                int n = wn + nt*8 + gid;
                bh[nt][0] = LD32(pbh, n, kb);  bh[nt][1] = LD32(pbh, n, kb+8);
                bl[nt][0] = LD32(pbl, n, kb);  bl[nt][1] = LD32(pbl, n, kb+8);
            }
            #pragma unroll
            for (int mt = 0; mt < 4; mt++)
                #pragma unroll
                for (int nt = 0; nt < 4; nt++) mma16(acc[mt][nt], ah[mt], bh[nt]);
            #pragma unroll
            for (int mt = 0; mt < 4; mt++)
                #pragma unroll
                for (int nt = 0; nt < 4; nt++) mma16(acc[mt][nt], ah[mt], bl[nt]);
            #pragma unroll
            for (int mt = 0; mt < 4; mt++)
                #pragma unroll
                for (int nt = 0; nt < 4; nt++) mma16(acc[mt][nt], al[mt], bh[nt]);
        }
    };

    fetch(0);
    stage(0);
    __syncthreads();

    for (int kt = 0; kt < 512; kt += KC) {
        const int cur = (kt / KC) & 1;
        const bool more = (kt + KC) < 512;
        if (more) fetch(kt + KC);
        compute(cur);
        if (more) stage(cur ^ 1);
        __syncthreads();
    }

    #pragma unroll
    for (int mt = 0; mt < 4; mt++) {
        #pragma unroll
        for (int nt = 0; nt < 4; nt++) {
            int r0 = by*128 + wm + mt*16 + gid;
            int cc = bx*128 + wn + nt*8 + tig*2;
            float2 v0 = make_float2(acc[mt][nt][0], acc[mt][nt][1]);
            float2 v1 = make_float2(acc[mt][nt][2], acc[mt][nt][3]);
            if (RES) {
                float2 q0 = *(const float2*)(res + (size_t)r0 * DD + cc);
                float2 q1 = *(const float2*)(res + (size_t)(r0+8) * DD + cc);
                v0.x += q0.x; v0.y += q0.y; v1.x += q1.x; v1.y += q1.y;
            }
            *(float2*)(C + (size_t)r0     * DD + cc) = v0;
            *(float2*)(C + (size_t)(r0+8) * DD + cc) = v1;
        }
    }
}

__global__ void __launch_bounds__(256)
qkv_mm(const __nv_bfloat16* __restrict__ Ah, const __nv_bfloat16* __restrict__ Al,
       const __nv_bfloat16* __restrict__ WhL, const __nv_bfloat16* __restrict__ WlL,
       float* __restrict__ Cq, float* __restrict__ Ck, float* __restrict__ Cv) {
    int z = blockIdx.z;
    const __nv_bfloat16* Bh = WhL + (size_t)z * DD * DD;
    const __nv_bfloat16* Bl = WlL + (size_t)z * DD * DD;
    float* C = (z == 0) ? Cq : (z == 1) ? Ck : Cv;
    bf16_gemm_body<false>(Ah, Al, Bh, Bl, C, nullptr, blockIdx.x, blockIdx.y);
}

__global__ void __launch_bounds__(256)
o_mm(const __nv_bfloat16* __restrict__ Ah, const __nv_bfloat16* __restrict__ Al,
     const __nv_bfloat16* __restrict__ Bh, const __nv_bfloat16* __restrict__ Bl,
     float* __restrict__ C, const float* __restrict__ res) {
    bf16_gemm_body<true>(Ah, Al, Bh, Bl, C, res, blockIdx.x, blockIdx.y);
}

// ---------------- edge pass 1: logits only (no atomics) -----------------------
__global__ void edge_logits(const float* __restrict__ dre,
                            const float* __restrict__ dae,
                            const float* __restrict__ rpe) {
    int warp = (blockIdx.x * blockDim.x + threadIdx.x) >> 5;
    int lane = threadIdx.x & 31;
    int total = g_starts[NB];
    if (warp >= total) return;
    int e = warp;
    int src = g_src[e], tgt = g_tgt[e];
    int d0 = lane * 2;
    int dr = g_dr[e], da = g_da[e], rp = g_rp[e];
    const float2 drv = *(const float2*)(dre + dr*DKK + d0);
    const float2 dav = *(const float2*)(dae + da*DKK + d0);
    const float2 rpv = *(const float2*)(rpe + rp*DKK + d0);
    float r0 = drv.x + dav.x + rpv.x;
    float r1 = drv.y + dav.y + rpv.y;
    #pragma unroll
    for (int h = 0; h < HH; h++) {
        const float2 kk = *(const float2*)(g_K + (size_t)src*DD + h*DKK + d0);
        const float2 qq = *(const float2*)(g_Q + (size_t)tgt*DD + h*DKK + d0);
        float p = qq.x * (kk.x + r0) + qq.y * (kk.y + r1);
        #pragma unroll
        for (int off = 16; off; off >>= 1) p += __shfl_xor_sync(0xffffffffu, p, off);
        if (lane == 0) g_ev[(size_t)e*HH + h] = p * 0.125f;  // 1/sqrt(64)
    }
}

// ---------------- edge pass 2 (fused): softmax + aggregate, warp per node -----
// CSR walk; aggregation emitted DIRECTLY as bf16 hi/lo splits (o_mm consumes
// only the splits; no float AGG buffer, no separate split pass, no atomics).
__global__ void node_attn(const float* __restrict__ dre,
                          const float* __restrict__ dae,
                          const float* __restrict__ rpe,
                          float* __restrict__ alpha_out) {
    int node = (blockIdx.x * blockDim.x + threadIdx.x) >> 5;
    if (node >= NN) return;
    int lane = threadIdx.x & 31;
    int r0 = g_rowptr[node], r1 = g_rowptr[node+1];
    int d0 = lane * 2;

    float m[HH];
    #pragma unroll
    for (int h = 0; h < HH; h++) m[h] = -1e30f;
    for (int i = r0; i < r1; i++) {
        int e = g_eid[i];
        #pragma unroll
        for (int h = 0; h < HH; h++) m[h] = fmaxf(m[h], g_ev[(size_t)e*HH + h]);
    }
    float s[HH];
    #pragma unroll
    for (int h = 0; h < HH; h++) s[h] = 0.f;
    for (int i = r0; i < r1; i++) {
        int e = g_eid[i];
        #pragma unroll
        for (int h = 0; h < HH; h++) s[h] += __expf(g_ev[(size_t)e*HH + h] - m[h]);
    }
    float inv[HH];
    #pragma unroll
    for (int h = 0; h < HH; h++) inv[h] = 1.f / (s[h] + 1e-9f);

    float acc[2*HH];
    #pragma unroll
    for (int i = 0; i < 2*HH; i++) acc[i] = 0.f;

    for (int i = r0; i < r1; i++) {
        int e = g_eid[i];
        int src = g_src[e];
        int dr = g_dr[e], da = g_da[e], rp = g_rp[e];
        const float2 drv = *(const float2*)(dre + dr*DKK + d0);
        const float2 dav = *(const float2*)(dae + da*DKK + d0);
        const float2 rpv = *(const float2*)(rpe + rp*DKK + d0);
        float rr0 = drv.x + dav.x + rpv.x;
        float rr1 = drv.y + dav.y + rpv.y;
        float a[HH];
        #pragma unroll
        for (int h = 0; h < HH; h++)
            a[h] = __expf(g_ev[(size_t)e*HH + h] - m[h]) * inv[h];
        float av = a[0];
        #pragma unroll
        for (int h = 1; h < HH; h++) if (lane == h) av = a[h];
        if (lane < HH) alpha_out[(size_t)e*HH + lane] = av;
        #pragma unroll
        for (int h = 0; h < HH; h++) {
            const float2 vv = *(const float2*)(g_V + (size_t)src*DD + h*DKK + d0);
            acc[2*h]   += a[h] * (vv.x + rr0);
            acc[2*h+1] += a[h] * (vv.y + rr1);
        }
    }
    #pragma unroll
    for (int h = 0; h < HH; h++) {
        size_t off = (size_t)node*DD + h*DKK + d0;
        __nv_bfloat16 h0 = __float2bfloat16_rn(acc[2*h]);
        __nv_bfloat16 h1 = __float2bfloat16_rn(acc[2*h+1]);
        __nv_bfloat16 l0 = __float2bfloat16_rn(acc[2*h]   - __bfloat162float(h0));
        __nv_bfloat16 l1 = __float2bfloat16_rn(acc[2*h+1] - __bfloat162float(h1));
        *(__nv_bfloat162*)(g_Ah + off) = __halves2bfloat162(h0, h1);
        *(__nv_bfloat162*)(g_Al + off) = __halves2bfloat162(l0, l1);
    }
}

// ---------------- LayerNorm (+ fused bf16 split of output when EMIT) ----------
__global__ void ln_kernel(const float* __restrict__ x,
                          const float* __restrict__ scale,
                          const float* __restrict__ bias,
                          float* __restrict__ out, int do_relu, int emit_split) {
    int row = blockIdx.x;
    const float* xr = x + (size_t)row * DD;
    int t = threadIdx.x;
    float v[4];
    float s = 0.f;
    #pragma unroll
    for (int i = 0; i < 4; i++) { v[i] = xr[t + i*128]; s += v[i]; }
    __shared__ float red[4];
    #pragma unroll
    for (int off = 16; off; off >>= 1) s += __shfl_xor_sync(0xffffffffu, s, off);
    if ((t & 31) == 0) red[t >> 5] = s;
    __syncthreads();
    s = red[0] + red[1] + red[2] + red[3];
    float mu = s * (1.f / DD);
    float vs = 0.f;
    #pragma unroll
    for (int i = 0; i < 4; i++) { float d = v[i] - mu; vs += d*d; }
    __syncthreads();
    #pragma unroll
    for (int off = 16; off; off >>= 1) vs += __shfl_xor_sync(0xffffffffu, vs, off);
    if ((t & 31) == 0) red[t >> 5] = vs;
    __syncthreads();
    vs = red[0] + red[1] + red[2] + red[3];
    float rstd = rsqrtf(vs * (1.f / DD) + 1e-5f);
    float* orow = out + (size_t)row * DD;
    #pragma unroll
    for (int i = 0; i < 4; i++) {
        int d = t + i*128;
        float y = (v[i] - mu) * rstd * scale[d] + bias[d];
        if (do_relu) y = fmaxf(y, 0.f);
        orow[d] = y;
        if (emit_split) {
            __nv_bfloat16 hh = __float2bfloat16_rn(y);
            g_Ah[(size_t)row*DD + d] = hh;
            g_Al[(size_t)row*DD + d] = __float2bfloat16_rn(y - __bfloat162float(hh));
        }
    }
}

// ---------------- host orchestration -----------------------------------------
extern "C" void kernel_launch(void* const* d_in, const int* in_sizes, int n_in,
                              void* d_out, int out_size) {
    const float* inp        = (const float*)d_in[0];
    const int*   edge_len   = (const int*)  d_in[2];
    const int*   edge_index = (const int*)  d_in[3];
    const int*   rp_in      = (const int*)  d_in[4];
    const int*   dr_in      = (const int*)  d_in[6];
    const int*   da_in      = (const int*)  d_in[7];
    const float* Wq         = (const float*)d_in[14];
    const float* Wk         = (const float*)d_in[15];
    const float* Wv         = (const float*)d_in[16];
    const float* Wo         = (const float*)d_in[17];
    const float* dre        = (const float*)d_in[18];
    const float* dae        = (const float*)d_in[19];
    const float* rpe        = (const float*)d_in[20];
    const float* ln_s       = (const float*)d_in[21];
    const float* ln_b       = (const float*)d_in[22];

    float* out   = (float*)d_out;
    float* reps  = out;                             // [L, N, D]
    float* attns = out + (size_t)LL * NN * DD;      // [L, BE, H]

    float *Qp, *Kp, *Vp, *LINp;
    __nv_bfloat16 *Ahp, *Alp, *Whp, *Wlp;
    cudaGetSymbolAddress((void**)&Qp,   g_Q);
    cudaGetSymbolAddress((void**)&Kp,   g_K);
    cudaGetSymbolAddress((void**)&Vp,   g_V);
    cudaGetSymbolAddress((void**)&LINp, g_LIN);
    cudaGetSymbolAddress((void**)&Ahp,  g_Ah);
    cudaGetSymbolAddress((void**)&Alp,  g_Al);
    cudaGetSymbolAddress((void**)&Whp,  g_Wh);
    cudaGetSymbolAddress((void**)&Wlp,  g_Wl);

    cudaFuncSetAttribute(qkv_mm, cudaFuncAttributeMaxDynamicSharedMemorySize, GSM);
    cudaFuncSetAttribute(o_mm,   cudaFuncAttributeMaxDynamicSharedMemorySize, GSM);

    const int splitA_grid = (NN*DD/4 + 255)/256;

    // Launch order chosen so qkv_mm is the 4th launch (ncu capture target).
    prep_kernel<<<1, 32>>>(edge_len);                                   // 1
    split_w<<<dim3(16, 16, 8), dim3(32, 8)>>>(Wq, Wk, Wv, Wo);          // 2
    split_a<<<splitA_grid, 256>>>(inp);                                 // 3
    qkv_mm<<<dim3(4, 128, 3), 256, GSM>>>(Ahp, Alp,                     // 4 (l=0)
        Whp, Wlp, Qp, Kp, Vp);

    // CSR build + output padding (independent of QKV)
    zero_aux<<<(NN + 255)/256, 256>>>();
    flatten_kernel<<<(NB*EE + 255)/256, 256>>>(edge_len, edge_index, dr_in, da_in, rp_in);
    scan_deg<<<1, 1024>>>();
    scatter_csr<<<(BEE + 255)/256, 256>>>();
    zero_f<<<(LL*BEE*HH + 255)/256, 256>>>(attns, LL*BEE*HH);

    for (int l = 0; l < LL; l++) {
        if (l > 0)
            qkv_mm<<<dim3(4, 128, 3), 256, GSM>>>(Ahp, Alp,
                Whp + (size_t)l*4*DD*DD, Wlp + (size_t)l*4*DD*DD, Qp, Kp, Vp);

        const float* drl = dre + (size_t)l * 50 * DKK;
        const float* dal = dae + (size_t)l * 3  * DKK;
        const float* rpl = rpe + (size_t)l * 21 * DKK;

        edge_logits<<<BEE/8, 256>>>(drl, dal, rpl);
        node_attn<<<(NN*32 + 255)/256, 256>>>(drl, dal, rpl,
                                              attns + (size_t)l * BEE * HH);

        const float* resid = (l == 0) ? inp : (reps + (size_t)(l-1) * NN * DD);
        o_mm<<<dim3(4, 128, 1), 256, GSM>>>(Ahp, Alp,
            Whp + (size_t)(l*4+3)*DD*DD, Wlp + (size_t)(l*4+3)*DD*DD, LINp, resid);

        float* rep_l = reps + (size_t)l * NN * DD;
        ln_kernel<<<NN, 128>>>(LINp, ln_s + (size_t)l * DD, ln_b + (size_t)l * DD,
                               rep_l, (l < LL - 1) ? 1 : 0, (l < LL - 1) ? 1 : 0);
    }
}